// round 2
// baseline (speedup 1.0000x reference)
#include <cuda_runtime.h>
#include <stdint.h>

// out[b,t,n,f] = in[b,t,n,f] * ((n < set_size[b,t]) ? (ALPHA+BETA) : 0)
// B=32, T=64, N=128, F=256, fp32. Pure HBM-bound elementwise masked scale.
// NOTE: jax "int64" without x64 enabled is actually int32 -> read as int.

#define B_DIM 32
#define T_DIM 64
#define N_DIM 128
#define F_DIM 256
#define SCALE 1.1f

// Total elements: 32*64*128*256 = 67,108,864 ; float4 count = 16,777,216
// float4s per (b,t,n) row: F/4 = 64  -> row = idx >> 6
// n = row & (N-1) ; bt = row >> 7

__global__ void __launch_bounds__(256, 8)
er_mask_scale_kernel(const float4* __restrict__ in,
                     const int* __restrict__ set_size,
                     float4* __restrict__ out)
{
    unsigned idx = blockIdx.x * blockDim.x + threadIdx.x;  // 0 .. 16,777,215
    unsigned row = idx >> 6;            // (b,t,n) row index, 0 .. 262143
    unsigned n   = row & (N_DIM - 1);   // 0 .. 127
    unsigned bt  = row >> 7;            // 0 .. 2047

    int ss = __ldg(&set_size[bt]);      // broadcast, L2-resident
    float s = ((int)n < ss) ? SCALE : 0.0f;

    float4 v = __ldg(&in[idx]);
    v.x *= s; v.y *= s; v.z *= s; v.w *= s;
    out[idx] = v;
}

extern "C" void kernel_launch(void* const* d_in, const int* in_sizes, int n_in,
                              void* d_out, int out_size)
{
    const float4* in = (const float4*)d_in[0];
    const int* ss = (const int*)d_in[1];
    float4* out = (float4*)d_out;

    const unsigned total_f4 = (unsigned)(B_DIM * T_DIM * N_DIM * (F_DIM / 4)); // 16,777,216
    const unsigned threads = 256;
    const unsigned blocks = total_f4 / threads; // 65,536

    er_mask_scale_kernel<<<blocks, threads>>>(in, ss, out);
}

// round 3
// speedup vs baseline: 1.1388x; 1.1388x over previous
#include <cuda_runtime.h>
#include <stdint.h>

// out[b,t,n,f] = in[b,t,n,f] * ((n < set_size[b,t]) ? (ALPHA+BETA) : 0)
// B=32, T=64, N=128, F=256, fp32.
// set_size ~ uniform[0,N] => ~half the rows are zero. For those, skip the
// input load entirely (output is zero regardless). Warp-uniform predicate:
// one warp = 32 float4 = 128 floats = exactly half of one F=256 row.
// Expected traffic: 256MiB writes + ~128MiB reads = ~384MiB vs 512MiB.

#define B_DIM 32
#define T_DIM 64
#define N_DIM 128
#define F_DIM 256
#define SCALE 1.1f

__global__ void __launch_bounds__(256, 8)
er_mask_scale_kernel(const float4* __restrict__ in,
                     const int* __restrict__ set_size,
                     float4* __restrict__ out)
{
    unsigned idx = blockIdx.x * blockDim.x + threadIdx.x;  // 0 .. 16,777,215
    unsigned row = idx >> 6;            // (b,t,n) row index, 0 .. 262143
    unsigned n   = row & (N_DIM - 1);   // 0 .. 127
    unsigned bt  = row >> 7;            // 0 .. 2047

    int ss = __ldg(&set_size[bt]);      // broadcast, L2-resident

    if ((int)n < ss) {
        float4 v = __ldg(&in[idx]);
        v.x *= SCALE; v.y *= SCALE; v.z *= SCALE; v.w *= SCALE;
        out[idx] = v;
    } else {
        out[idx] = make_float4(0.0f, 0.0f, 0.0f, 0.0f);
    }
}

extern "C" void kernel_launch(void* const* d_in, const int* in_sizes, int n_in,
                              void* d_out, int out_size)
{
    const float4* in = (const float4*)d_in[0];
    const int* ss = (const int*)d_in[1];
    float4* out = (float4*)d_out;

    const unsigned total_f4 = (unsigned)(B_DIM * T_DIM * N_DIM * (F_DIM / 4)); // 16,777,216
    const unsigned threads = 256;
    const unsigned blocks = total_f4 / threads; // 65,536

    er_mask_scale_kernel<<<blocks, threads>>>(in, ss, out);
}

// round 4
// speedup vs baseline: 1.3137x; 1.1536x over previous
#include <cuda_runtime.h>
#include <stdint.h>

// out[b,t,n,f] = in[b,t,n,f] * ((n < set_size[b,t]) ? (ALPHA+BETA) : 0)
// B=32, T=64, N=128, F=256, fp32.
// ~half the rows are zero (set_size ~ U[0,128]) -> skip input load there.
// 4 float4 per thread to restore MLP: predicates first, batched loads,
// then stores. Warp covers 32 consecutive f4 = half an F-row, so the
// mask predicate is warp-uniform each iteration.

#define N_DIM 128
#define SCALE 1.1f
#define F4_PER_THREAD 4
#define THREADS 256

// total f4 = 32*64*128*(256/4) = 16,777,216

__global__ void __launch_bounds__(THREADS, 8)
er_mask_scale_kernel(const float4* __restrict__ in,
                     const int* __restrict__ set_size,
                     float4* __restrict__ out)
{
    // block handles 1024 contiguous float4 (= 16 rows of 64 f4)
    unsigned base = blockIdx.x * (THREADS * F4_PER_THREAD) + threadIdx.x;

    unsigned idx[F4_PER_THREAD];
    bool     live[F4_PER_THREAD];

    #pragma unroll
    for (int i = 0; i < F4_PER_THREAD; i++) {
        idx[i] = base + i * THREADS;
        unsigned row = idx[i] >> 6;           // (b,t,n)
        unsigned n   = row & (N_DIM - 1);
        unsigned bt  = row >> 7;
        int ss = __ldg(&set_size[bt]);        // L2-resident broadcast
        live[i] = ((int)n < ss);
    }

    float4 v[F4_PER_THREAD];
    #pragma unroll
    for (int i = 0; i < F4_PER_THREAD; i++) {
        v[i] = make_float4(0.f, 0.f, 0.f, 0.f);
        if (live[i]) v[i] = __ldg(&in[idx[i]]);   // predicated, batched
    }

    #pragma unroll
    for (int i = 0; i < F4_PER_THREAD; i++) {
        if (live[i]) {
            v[i].x *= SCALE; v[i].y *= SCALE; v[i].z *= SCALE; v[i].w *= SCALE;
        }
        out[idx[i]] = v[i];
    }
}

extern "C" void kernel_launch(void* const* d_in, const int* in_sizes, int n_in,
                              void* d_out, int out_size)
{
    const float4* in = (const float4*)d_in[0];
    const int* ss = (const int*)d_in[1];
    float4* out = (float4*)d_out;

    const unsigned total_f4 = 16777216u;
    const unsigned blocks = total_f4 / (THREADS * F4_PER_THREAD); // 16384

    er_mask_scale_kernel<<<blocks, THREADS>>>(in, ss, out);
}